// round 11
// baseline (speedup 1.0000x reference)
#include <cuda_runtime.h>
#include <cstdint>

// Sampler: temperature 0.8, top-k (from input), top-p 0.9, inverse-CDF multinomial.
// One block per row; single streaming pass; histogram threshold selection.
// OUTPUT IS WRITTEN AS float32 (ids as float values): ten rounds of exactly-1.0
// rel_err are only explained by the compare buffer being float32 while we wrote
// int32 bit patterns (denormals ~ 0 -> ||0-ref||/||ref|| == 1.000000 exactly).

#define NT 256
#define F4PT 8
#define CHUNK_F4 (NT * F4PT)
#define NBINS 4096
#define BINSHIFT 20
#define BPT (NBINS / NT)
#define BUF_N 2560
#define EPI_N 512
#define MAXEPI 256

typedef unsigned long long u64;
typedef unsigned int u32;

__device__ __forceinline__ u32 flip32(u32 f) {
    return (f & 0x80000000u) ? ~f : (f | 0x80000000u);
}
__device__ __forceinline__ u32 unflip32(u32 g) {
    return (g & 0x80000000u) ? (g & 0x7FFFFFFFu) : ~g;
}

struct Sh {
    int cnt;
    int cnt2;
    u32 thr1, thr2;
    float x[MAXEPI];
    float e[MAXEPI];
    int   id[MAXEPI];
};

__device__ void select_threshold(const u32* __restrict__ hist, int target,
                                 u32* res_thr, u32* partial) {
    const int tid = threadIdx.x;
    u32 s = 0;
    const int hi = NBINS - BPT * tid;
#pragma unroll
    for (int i = 0; i < BPT; i++) s += hist[hi - 1 - i];
    partial[tid] = s;
    __syncthreads();
    if (tid < 32) {
        u32 s8 = 0;
#pragma unroll
        for (int j = 0; j < 8; j++) s8 += partial[tid * 8 + j];
        u32 c = s8;
#pragma unroll
        for (int d = 1; d < 32; d <<= 1) {
            u32 nb = __shfl_up_sync(0xffffffffu, c, d);
            if (tid >= d) c += nb;
        }
        unsigned ball = __ballot_sync(0xffffffffu, c >= (u32)target);
        if (ball == 0) {
            if (tid == 31) *res_thr = 0u;
        } else {
            int L = __ffs(ball) - 1;
            if (tid == L) {
                u32 cc = c - s8;
                u32 thr = 0u;
                bool done = false;
                for (int t2 = 8 * L; t2 < 8 * L + 8 && !done; t2++) {
                    const int h2 = NBINS - BPT * t2;
                    for (int b = h2 - 1; b >= h2 - BPT; b--) {
                        cc += hist[b];
                        if (cc >= (u32)target) { thr = ((u32)b) << BINSHIFT; done = true; break; }
                    }
                }
                *res_thr = thr;
            }
        }
    }
    __syncthreads();
}

__device__ __forceinline__ void warp_append(u64* buf, int* cnt, bool p, u64 key) {
    unsigned m = __ballot_sync(0xffffffffu, p);
    if (m == 0) return;
    int leader = __ffs(m) - 1;
    int lane = threadIdx.x & 31;
    int base = 0;
    if (lane == leader) base = atomicAdd(cnt, __popc(m));
    base = __shfl_sync(0xffffffffu, base, leader);
    if (p) {
        int off = base + __popc(m & ((1u << lane) - 1u));
        if (off < BUF_N) buf[off] = key;
    }
}

__global__ __launch_bounds__(NT)
void Sampler_24446953849417_kernel(const float* __restrict__ logits,
                                   const float* __restrict__ u,
                                   const int* __restrict__ kptr,
                                   float* __restrict__ out, int V)
{
    __shared__ u32 hist[NBINS];
    __shared__ u64 buf[BUF_N];
    __shared__ u64 ep[EPI_N];
    __shared__ Sh sh;
    __shared__ u32 partial[NT];

    const int row = blockIdx.x;
    const int tid = threadIdx.x;

    const float4* __restrict__ rp =
        reinterpret_cast<const float4*>(logits + (size_t)row * (size_t)V);
    const int nf4 = V >> 2;
    const int nchunks = (nf4 + CHUNK_F4 - 1) / CHUNK_F4;
    const float NEG = __int_as_float(0xff800000);

    int k = 50;
    if (kptr) {
        int kv = kptr[0];
        if (kv >= 1 && kv <= 100000) k = kv;
        else {
            float kf = __int_as_float(kv);
            if (kf >= 1.0f && kf <= 100000.0f) k = (int)kf;
        }
    }
    k = max(1, min(k, MAXEPI));

    for (int i = tid; i < NBINS; i += NT) hist[i] = 0u;
    if (tid == 0) { sh.cnt = 0; sh.cnt2 = 0; }

    // ---- chunk 0 into registers ----
    float4 v0[F4PT];
#pragma unroll
    for (int q = 0; q < F4PT; q++) {
        int f4i = q * NT + tid;
        v0[q] = (f4i < nf4) ? rp[f4i] : make_float4(NEG, NEG, NEG, NEG);
    }
    __syncthreads();

    // ---- chunk-0 histogram (primes collection threshold) ----
#pragma unroll
    for (int q = 0; q < F4PT; q++) {
        int f4i = q * NT + tid;
        if (f4i < nf4) {
            const float vv[4] = {v0[q].x, v0[q].y, v0[q].z, v0[q].w};
#pragma unroll
            for (int e = 0; e < 4; e++)
                atomicAdd(&hist[flip32(__float_as_uint(vv[e])) >> BINSHIFT], 1u);
        }
    }
    __syncthreads();

    // thr1 <= chunk0-kth <= row-kth : never excludes a true top-k element
    select_threshold(hist, k, &sh.thr1, partial);
    const u32 thr1 = sh.thr1;

#pragma unroll
    for (int q = 0; q < F4PT; q++) {
        int f4i = q * NT + tid;
        const float vv[4] = {v0[q].x, v0[q].y, v0[q].z, v0[q].w};
#pragma unroll
        for (int e = 0; e < 4; e++) {
            u32 fb = flip32(__float_as_uint(vv[e]));
            bool p = (f4i < nf4) && (fb >= thr1);
            u64 key = ((u64)fb << 32) | (u32)(0xFFFFFFFFu - (u32)(f4i * 4 + e));
            warp_append(buf, &sh.cnt, p, key);
        }
    }

    // ---- stream remaining chunks (no barriers in loop) ----
    for (int ch = 1; ch < nchunks; ch++) {
        const int base = ch * CHUNK_F4;
        float4 v[F4PT];
#pragma unroll
        for (int q = 0; q < F4PT; q++) {
            int f4i = base + q * NT + tid;
            v[q] = (f4i < nf4) ? rp[f4i] : make_float4(NEG, NEG, NEG, NEG);
        }
#pragma unroll
        for (int q = 0; q < F4PT; q++) {
            int f4i = base + q * NT + tid;
            const float vv[4] = {v[q].x, v[q].y, v[q].z, v[q].w};
#pragma unroll
            for (int e = 0; e < 4; e++) {
                u32 fb = flip32(__float_as_uint(vv[e]));
                bool p = (f4i < nf4) && (fb >= thr1);
                u64 key = ((u64)fb << 32) | (u32)(0xFFFFFFFFu - (u32)(f4i * 4 + e));
                warp_append(buf, &sh.cnt, p, key);
            }
        }
    }
    if (tid < 32) {   // scalar tail (V % 4 != 0); warp-collective call from warp 0
        int idx = nf4 * 4 + tid;
        bool inb = idx < V;
        float val = inb ? logits[(size_t)row * (size_t)V + idx] : NEG;
        u32 fb = flip32(__float_as_uint(val));
        u64 key = ((u64)fb << 32) | (u32)(0xFFFFFFFFu - (u32)idx);
        warp_append(buf, &sh.cnt, inb && (fb >= thr1), key);
    }
    __syncthreads();

    // ---- phase 2: exact-k among candidates ----
    const int cnt = min(sh.cnt, BUF_N);
    for (int i = tid; i < NBINS; i += NT) hist[i] = 0u;
    __syncthreads();
    for (int i = tid; i < cnt; i += NT)
        atomicAdd(&hist[(u32)(buf[i] >> 32) >> BINSHIFT], 1u);
    __syncthreads();
    select_threshold(hist, k, &sh.thr2, partial);
    const u32 thr2 = sh.thr2;

    for (int i = tid; i < cnt; i += NT) {
        u64 key = buf[i];
        if ((u32)(key >> 32) >= thr2) {
            int p = atomicAdd(&sh.cnt2, 1);
            if (p < EPI_N) ep[p] = key;
        }
    }
    __syncthreads();
    const int c2 = min(sh.cnt2, EPI_N);

    // ---- bitonic sort finalists desc (value desc, index asc on ties) ----
    int n = 1;
    while (n < c2) n <<= 1;
    for (int j = c2 + tid; j < n; j += NT) ep[j] = 0ull;
    __syncthreads();
    for (int k2 = 2; k2 <= n; k2 <<= 1) {
        for (int s = k2 >> 1; s > 0; s >>= 1) {
            for (int j = tid; j < n; j += NT) {
                int l = j ^ s;
                if (l > j) {
                    u64 a = ep[j], b = ep[l];
                    bool desc = ((j & k2) == 0);
                    if ((a < b) == desc) { ep[j] = b; ep[l] = a; }
                }
            }
            __syncthreads();
        }
    }

    // ---- unpack: IEEE division (fast-math-immune), matches JAX logits/0.8 ----
    const int L = min(c2, MAXEPI);
    for (int i = tid; i < L; i += NT) {
        u64 key = ep[i];
        sh.x[i]  = __fdiv_rn(__uint_as_float(unflip32((u32)(key >> 32))), 0.8f);
        sh.id[i] = (int)(0xFFFFFFFFu - (u32)(key & 0xFFFFFFFFu));
    }
    __syncthreads();

    // ---- serial epilogue (exact reference arithmetic order) ----
    if (tid == 0) {
        int ans = V;
        if (L >= 1) {
            int kc = min(k, L);
            const float x0 = sh.x[0];
            const float kth = sh.x[kc - 1];
            int kk = kc;
            while (kk < L && sh.x[kk] >= kth) kk++;   // keep ties, as reference

            // softmax over kept set in sorted (desc) order
            float d1 = 0.f;
            for (int i = 0; i < kk; i++) {
                float ee = expf(__fadd_rn(sh.x[i], -x0));
                sh.e[i] = ee;
                d1 = __fadd_rn(d1, ee);
            }
            // nucleus: sorted token i removed iff cdf[i-1] > 0.9 -> survivors = prefix
            float cprev = 0.f;
            int m = 0;
            for (int i = 0; i < kk; i++) {
                if (i > 0 && cprev > 0.9f) break;
                m++;
                cprev = __fadd_rn(cprev, __fdiv_rn(sh.e[i], d1));
            }
            // sort survivors by vocab index ascending (final cumsum is vocab order)
            for (int i = 1; i < m; i++) {
                int idv = sh.id[i]; float ev = sh.e[i]; int j = i - 1;
                while (j >= 0 && sh.id[j] > idv) {
                    sh.id[j + 1] = sh.id[j]; sh.e[j + 1] = sh.e[j]; j--;
                }
                sh.id[j + 1] = idv; sh.e[j + 1] = ev;
            }
            // final softmax denominator in vocab order (reference cumsum basis)
            float d2 = 0.f;
            for (int i = 0; i < m; i++) d2 = __fadd_rn(d2, sh.e[i]);

            // next_id = sum(cumsum(probs) <= u) = first survivor with S > u (V if none)
            const float uu = u ? u[row] : 0.5f;
            float S = 0.f;
            for (int i = 0; i < m; i++) {
                S = __fadd_rn(S, __fdiv_rn(sh.e[i], d2));
                if (S > uu) { ans = sh.id[i]; break; }
            }
        }
        out[row] = (float)ans;   // OUTPUT AS float32 (ids < 2^24 are exact)
    }
}

extern "C" void kernel_launch(void* const* d_in, const int* in_sizes, int n_in,
                              void* d_out, int out_size) {
    int li = 0;
    for (int i = 1; i < n_in; i++)
        if (in_sizes[i] > in_sizes[li]) li = i;

    const int B = out_size;
    const float* logits = (const float*)d_in[li];
    const float* u = nullptr;
    const int* kp = nullptr;
    for (int i = 0; i < n_in; i++) {
        if (i == li) continue;
        if (in_sizes[i] == B) u = (const float*)d_in[i];
        else if (in_sizes[i] == 1) kp = (const int*)d_in[i];
    }
    if (!u) {
        for (int i = 0; i < n_in; i++)
            if (i != li && in_sizes[i] != 1) { u = (const float*)d_in[i]; break; }
    }

    int V = in_sizes[li] / B;
    if (V * B != in_sizes[li]) {
        int Vb = in_sizes[li] / 4 / B;
        if (Vb * B * 4 == in_sizes[li]) V = Vb;
    }

    Sampler_24446953849417_kernel<<<B, NT>>>(logits, u, kp, (float*)d_out, V);
}